// round 5
// baseline (speedup 1.0000x reference)
#include <cuda_runtime.h>
#include <cuda_fp16.h>
#include <cstdint>

// ---------------- problem constants ----------------
#define MDIM 65536      // B*S
#define KDIM 768        // D
#define NDIM 2304       // 3*D
#define RNK  4

#define BM 128
#define BN 256
#define BK 32           // halves per K-step
#define KITERS (KDIM / BK)   // 24
#define STAGES 4

// smem stage layout: A 128 rows x 80B (32 halves + 16B pad), B 256 rows x 80B
#define AROW_B   80
#define A_BYTES  (128 * AROW_B)      // 10240
#define B_BYTES  (256 * AROW_B)      // 20480
#define STAGE_B  (A_BYTES + B_BYTES) // 30720
#define SMEM_TOTAL (STAGES * STAGE_B) // 122880

// ---------------- device scratch (no allocations allowed) ----------------
__device__ __half g_Xh[(size_t)MDIM * KDIM];   // fp16 X (96 MB)
__device__ __half g_Wh[(size_t)NDIM * KDIM];   // folded fp16 W_eff (3.4 MB)

// ---------------- helpers ----------------
__device__ __forceinline__ uint32_t smem_u32(const void* p) {
    return (uint32_t)__cvta_generic_to_shared(p);
}

__device__ __forceinline__ void cp_async16(uint32_t s, const void* g) {
    asm volatile("cp.async.cg.shared.global [%0], [%1], 16;" :: "r"(s), "l"(g));
}
#define CP_COMMIT() asm volatile("cp.async.commit_group;" ::: "memory")

#define LDSM_X4(r0, r1, r2, r3, addr) \
    asm volatile("ldmatrix.sync.aligned.m8n8.x4.shared.b16 {%0,%1,%2,%3}, [%4];" \
        : "=r"(r0), "=r"(r1), "=r"(r2), "=r"(r3) : "r"(addr))

#define MMA16816(d, a0, a1, a2, a3, b0, b1) \
    asm volatile("mma.sync.aligned.m16n8k16.row.col.f32.f16.f16.f32 " \
        "{%0,%1,%2,%3}, {%4,%5,%6,%7}, {%8,%9}, {%0,%1,%2,%3};" \
        : "+f"((d)[0]), "+f"((d)[1]), "+f"((d)[2]), "+f"((d)[3]) \
        : "r"(a0), "r"(a1), "r"(a2), "r"(a3), "r"(b0), "r"(b1))

// ---------------- prep kernels ----------------
__global__ void prep_w_kernel(const float* __restrict__ W,
                              const float* __restrict__ Aq, const float* __restrict__ Bq,
                              const float* __restrict__ Av, const float* __restrict__ Bv,
                              const float* __restrict__ s0) {
    int idx = blockIdx.x * 256 + threadIdx.x;   // exact: NDIM*KDIM
    int e = idx / KDIM;
    int d = idx - e * KDIM;
    float w = W[idx];
    float s = s0[0];
    if (e < KDIM) {                              // q slice
        float acc = 0.f;
#pragma unroll
        for (int r = 0; r < RNK; r++) acc += Aq[r * KDIM + d] * Bq[e * RNK + r];
        w = fmaf(s, acc, w);
    } else if (e >= 2 * KDIM) {                  // v slice
        int e2 = e - 2 * KDIM;
        float acc = 0.f;
#pragma unroll
        for (int r = 0; r < RNK; r++) acc += Av[r * KDIM + d] * Bv[e2 * RNK + r];
        w = fmaf(s, acc, w);
    }
    g_Wh[idx] = __float2half_rn(w);
}

__global__ void prep_x_kernel(const float4* __restrict__ x) {
    size_t i = (size_t)blockIdx.x * 256 + threadIdx.x;   // over MDIM*KDIM/8
    float4 v0 = x[2 * i];
    float4 v1 = x[2 * i + 1];
    __half2 h0 = __floats2half2_rn(v0.x, v0.y);
    __half2 h1 = __floats2half2_rn(v0.z, v0.w);
    __half2 h2 = __floats2half2_rn(v1.x, v1.y);
    __half2 h3 = __floats2half2_rn(v1.z, v1.w);
    uint4 o;
    o.x = *reinterpret_cast<uint32_t*>(&h0);
    o.y = *reinterpret_cast<uint32_t*>(&h1);
    o.z = *reinterpret_cast<uint32_t*>(&h2);
    o.w = *reinterpret_cast<uint32_t*>(&h3);
    reinterpret_cast<uint4*>(g_Xh)[i] = o;
}

// ---------------- main GEMM: 256 thr, 8 warps, warp tile 64x64 ----------------
__global__ __launch_bounds__(256, 1)
void gemm_f16_kernel(const __half* __restrict__ X, const __half* __restrict__ W,
                     const float* __restrict__ bias, float* __restrict__ out) {
    extern __shared__ char smem[];
    uint32_t sb = smem_u32(smem);
    int tid = threadIdx.x;
    int lane = tid & 31;
    int wid = tid >> 5;
    int warp_m = wid & 1;     // 2 m-warps (64 rows each)
    int warp_n = wid >> 1;    // 4 n-warps (64 cols each)

    int n0 = blockIdx.x * BN;   // 9 n-tiles fast-varying (X L2 reuse)
    int m0 = blockIdx.y * BM;

    // ---- per-thread cp.async src/dst ----
    // A: 512 x 16B chunks, 2 per thread; B: 1024 chunks, 4 per thread
    int arow = tid >> 2, ac = tid & 3;   // base pattern; +64 rows for t=1
    const __half* aSrc = X + (size_t)(m0 + arow) * KDIM + ac * 8;
    uint32_t aDst = sb + arow * AROW_B + ac * 16;

    const __half* bSrc = W + (size_t)(n0 + arow) * KDIM + ac * 8;
    uint32_t bDst = sb + A_BYTES + arow * AROW_B + ac * 16;

    // ---- ldmatrix lane addresses ----
    uint32_t aLds = sb + (warp_m * 64 + (lane & 15)) * AROW_B + ((lane >> 4) * 16);
    int t_ = lane >> 3;
    uint32_t bLds = sb + A_BYTES + (warp_n * 64 + (lane & 7) + (t_ >> 1) * 8) * AROW_B
                    + (t_ & 1) * 16;

    float acc[4][8][4];
#pragma unroll
    for (int mi = 0; mi < 4; mi++)
#pragma unroll
        for (int nj = 0; nj < 8; nj++)
#pragma unroll
            for (int q = 0; q < 4; q++) acc[mi][nj][q] = 0.f;

    // ---- prologue: fill STAGES-1 stages ----
#pragma unroll
    for (int s = 0; s < STAGES - 1; s++) {
        int koff = s * BK;
        uint32_t so = s * STAGE_B;
#pragma unroll
        for (int t = 0; t < 2; t++)
            cp_async16(aDst + so + t * 64 * AROW_B,
                       aSrc + (size_t)t * 64 * KDIM + koff);
#pragma unroll
        for (int t = 0; t < 4; t++)
            cp_async16(bDst + so + t * 64 * AROW_B,
                       bSrc + (size_t)t * 64 * KDIM + koff);
        CP_COMMIT();
    }

    for (int k = 0; k < KITERS; k++) {
        asm volatile("cp.async.wait_group 2;" ::: "memory");
        __syncthreads();

        // issue stage k+3 into slot (k-1)&3 (all warps past it per the sync)
        int kn = k + STAGES - 1;
        if (kn < KITERS) {
            int koff = kn * BK;
            uint32_t so = (kn & (STAGES - 1)) * STAGE_B;
#pragma unroll
            for (int t = 0; t < 2; t++)
                cp_async16(aDst + so + t * 64 * AROW_B,
                           aSrc + (size_t)t * 64 * KDIM + koff);
#pragma unroll
            for (int t = 0; t < 4; t++)
                cp_async16(bDst + so + t * 64 * AROW_B,
                           bSrc + (size_t)t * 64 * KDIM + koff);
        }
        CP_COMMIT();

        // ---- compute stage k ----
        uint32_t so = (k & (STAGES - 1)) * STAGE_B;
        uint32_t aB = aLds + so;
        uint32_t bB = bLds + so;
#pragma unroll
        for (int ks = 0; ks < 2; ks++) {
            uint32_t a[4][4];
#pragma unroll
            for (int mi = 0; mi < 4; mi++)
                LDSM_X4(a[mi][0], a[mi][1], a[mi][2], a[mi][3],
                        aB + mi * (16 * AROW_B) + ks * 32);
            uint32_t b[8][2];
#pragma unroll
            for (int p = 0; p < 4; p++)
                LDSM_X4(b[2 * p][0], b[2 * p][1], b[2 * p + 1][0], b[2 * p + 1][1],
                        bB + p * (16 * AROW_B) + ks * 32);
#pragma unroll
            for (int mi = 0; mi < 4; mi++)
#pragma unroll
                for (int nj = 0; nj < 8; nj++)
                    MMA16816(acc[mi][nj], a[mi][0], a[mi][1], a[mi][2], a[mi][3],
                             b[nj][0], b[nj][1]);
        }
    }

    // ---- epilogue: add bias, store fp32 ----
#pragma unroll
    for (int nj = 0; nj < 8; nj++) {
        int c = n0 + warp_n * 64 + nj * 8 + 2 * (lane & 3);
        float2 bb = *reinterpret_cast<const float2*>(bias + c);
#pragma unroll
        for (int mi = 0; mi < 4; mi++) {
            int r = m0 + warp_m * 64 + mi * 16 + (lane >> 2);
            float2 v0, v1;
            v0.x = acc[mi][nj][0] + bb.x;
            v0.y = acc[mi][nj][1] + bb.y;
            v1.x = acc[mi][nj][2] + bb.x;
            v1.y = acc[mi][nj][3] + bb.y;
            *reinterpret_cast<float2*>(out + (size_t)r * NDIM + c) = v0;
            *reinterpret_cast<float2*>(out + (size_t)(r + 8) * NDIM + c) = v1;
        }
    }
}

// ---------------- launch ----------------
extern "C" void kernel_launch(void* const* d_in, const int* in_sizes, int n_in,
                              void* d_out, int out_size) {
    (void)in_sizes; (void)n_in; (void)out_size;
    const float* x   = (const float*)d_in[0];
    const float* Wq  = (const float*)d_in[1];
    const float* b   = (const float*)d_in[2];
    const float* Aq  = (const float*)d_in[3];
    const float* Bq  = (const float*)d_in[4];
    const float* Av  = (const float*)d_in[5];
    const float* Bv  = (const float*)d_in[6];
    const float* s0  = (const float*)d_in[7];
    float* out = (float*)d_out;

    __half *xh, *wh;
    cudaGetSymbolAddress((void**)&xh, g_Xh);
    cudaGetSymbolAddress((void**)&wh, g_Wh);

    prep_w_kernel<<<(NDIM * KDIM) / 256, 256>>>(Wq, Aq, Bq, Av, Bv, s0);
    prep_x_kernel<<<(int)(((size_t)MDIM * KDIM / 8) / 256), 256>>>(
        (const float4*)x);

    cudaFuncSetAttribute(gemm_f16_kernel,
                         cudaFuncAttributeMaxDynamicSharedMemorySize, SMEM_TOTAL);
    gemm_f16_kernel<<<dim3(NDIM / BN, MDIM / BM, 1), 256, SMEM_TOTAL>>>(
        xh, wh, b, out);
}

// round 8
// speedup vs baseline: 1.1858x; 1.1858x over previous
#include <cuda_runtime.h>
#include <cuda_fp16.h>
#include <cstdint>

// ---------------- problem constants ----------------
#define MDIM 65536      // B*S
#define KDIM 768        // D
#define NDIM 2304       // 3*D
#define RNK  4

#define BM 128
#define BN 256
#define BK 32           // halves per K-step
#define KITERS (KDIM / BK)   // 24
#define STAGES 4

// smem stage layout: A 128 rows x 80B (32 halves + 16B pad), B 256 rows x 80B
#define AROW_B   80
#define A_BYTES  (128 * AROW_B)      // 10240
#define B_BYTES  (256 * AROW_B)      // 20480
#define STAGE_B  (A_BYTES + B_BYTES) // 30720
#define SMEM_TOTAL (STAGES * STAGE_B) // 122880

// ---------------- device scratch (no allocations allowed) ----------------
__device__ __half g_Xh[(size_t)MDIM * KDIM];   // fp16 X (96 MB)
__device__ __half g_Wh[(size_t)NDIM * KDIM];   // folded fp16 W_eff (3.4 MB)

// ---------------- helpers ----------------
__device__ __forceinline__ uint32_t smem_u32(const void* p) {
    return (uint32_t)__cvta_generic_to_shared(p);
}

__device__ __forceinline__ void cp_async16(uint32_t s, const void* g) {
    asm volatile("cp.async.cg.shared.global [%0], [%1], 16;" :: "r"(s), "l"(g));
}
#define CP_COMMIT() asm volatile("cp.async.commit_group;" ::: "memory")

#define LDSM_X4(r0, r1, r2, r3, addr) \
    asm volatile("ldmatrix.sync.aligned.m8n8.x4.shared.b16 {%0,%1,%2,%3}, [%4];" \
        : "=r"(r0), "=r"(r1), "=r"(r2), "=r"(r3) : "r"(addr))

// fp16-accumulate MMA: D(f16) = A(f16)*B(f16) + C(f16) — double-rate HMMA
#define MMA16816_F16(d, a0, a1, a2, a3, b0, b1) \
    asm volatile("mma.sync.aligned.m16n8k16.row.col.f16.f16.f16.f16 " \
        "{%0,%1}, {%2,%3,%4,%5}, {%6,%7}, {%0,%1};" \
        : "+r"((d)[0]), "+r"((d)[1]) \
        : "r"(a0), "r"(a1), "r"(a2), "r"(a3), "r"(b0), "r"(b1))

// ---------------- prep kernels ----------------
__global__ void prep_w_kernel(const float* __restrict__ W,
                              const float* __restrict__ Aq, const float* __restrict__ Bq,
                              const float* __restrict__ Av, const float* __restrict__ Bv,
                              const float* __restrict__ s0) {
    int idx = blockIdx.x * 256 + threadIdx.x;   // exact: NDIM*KDIM
    int e = idx / KDIM;
    int d = idx - e * KDIM;
    float w = W[idx];
    float s = s0[0];
    if (e < KDIM) {                              // q slice
        float acc = 0.f;
#pragma unroll
        for (int r = 0; r < RNK; r++) acc += Aq[r * KDIM + d] * Bq[e * RNK + r];
        w = fmaf(s, acc, w);
    } else if (e >= 2 * KDIM) {                  // v slice
        int e2 = e - 2 * KDIM;
        float acc = 0.f;
#pragma unroll
        for (int r = 0; r < RNK; r++) acc += Av[r * KDIM + d] * Bv[e2 * RNK + r];
        w = fmaf(s, acc, w);
    }
    g_Wh[idx] = __float2half_rn(w);
}

__global__ void prep_x_kernel(const float4* __restrict__ x) {
    size_t i = (size_t)blockIdx.x * 256 + threadIdx.x;   // over MDIM*KDIM/8
    float4 v0 = x[2 * i];
    float4 v1 = x[2 * i + 1];
    __half2 h0 = __floats2half2_rn(v0.x, v0.y);
    __half2 h1 = __floats2half2_rn(v0.z, v0.w);
    __half2 h2 = __floats2half2_rn(v1.x, v1.y);
    __half2 h3 = __floats2half2_rn(v1.z, v1.w);
    uint4 o;
    o.x = *reinterpret_cast<uint32_t*>(&h0);
    o.y = *reinterpret_cast<uint32_t*>(&h1);
    o.z = *reinterpret_cast<uint32_t*>(&h2);
    o.w = *reinterpret_cast<uint32_t*>(&h3);
    reinterpret_cast<uint4*>(g_Xh)[i] = o;
}

// ------- main GEMM: 512 thr, warp tile 32x64, fp16 accum in 2 chains -------
__global__ __launch_bounds__(512, 1)
void gemm_f16_kernel(const __half* __restrict__ X, const __half* __restrict__ W,
                     const float* __restrict__ bias, float* __restrict__ out) {
    extern __shared__ char smem[];
    uint32_t sb = smem_u32(smem);
    int tid = threadIdx.x;
    int lane = tid & 31;
    int wid = tid >> 5;
    int warp_m = wid & 3;     // 4 m-warps
    int warp_n = wid >> 2;    // 4 n-warps

    int n0 = blockIdx.x * BN;   // 9 n-tiles fast-varying (X L2 reuse)
    int m0 = blockIdx.y * BM;

    // ---- per-thread cp.async src/dst (A: 512 chunks, B: 1024 chunks) ----
    int arow = tid >> 2, ac = tid & 3;
    const __half* aSrc = X + (size_t)(m0 + arow) * KDIM + ac * 8;
    uint32_t aDst = sb + arow * AROW_B + ac * 16;

    int brow0 = tid >> 2;               // rows 0..127
    int brow1 = brow0 + 128;            // rows 128..255
    const __half* bSrc0 = W + (size_t)(n0 + brow0) * KDIM + ac * 8;
    const __half* bSrc1 = W + (size_t)(n0 + brow1) * KDIM + ac * 8;
    uint32_t bDst0 = sb + A_BYTES + brow0 * AROW_B + ac * 16;
    uint32_t bDst1 = sb + A_BYTES + brow1 * AROW_B + ac * 16;

    // ---- ldmatrix lane addresses ----
    uint32_t aLds = sb + (warp_m * 32 + (lane & 15)) * AROW_B + ((lane >> 4) * 16);
    int t_ = lane >> 3;
    uint32_t bLds = sb + A_BYTES + (warp_n * 64 + (lane & 7) + (t_ >> 1) * 8) * AROW_B
                    + (t_ & 1) * 16;

    // fp16 accumulators: 2 independent K-chains to bound rounding error
    uint32_t acch[2][2][8][2];
#pragma unroll
    for (int c = 0; c < 2; c++)
#pragma unroll
        for (int mi = 0; mi < 2; mi++)
#pragma unroll
            for (int nj = 0; nj < 8; nj++) {
                acch[c][mi][nj][0] = 0u;
                acch[c][mi][nj][1] = 0u;
            }

    // ---- prologue: fill 3 stages ----
#pragma unroll
    for (int s = 0; s < STAGES - 1; s++) {
        int koff = s * BK;
        uint32_t so = s * STAGE_B;
        cp_async16(aDst + so, aSrc + koff);
        cp_async16(bDst0 + so, bSrc0 + koff);
        cp_async16(bDst1 + so, bSrc1 + koff);
        CP_COMMIT();
    }

    for (int k = 0; k < KITERS; k++) {
        asm volatile("cp.async.wait_group 2;" ::: "memory");
        __syncthreads();

        // issue stage k+3 (slot of stage k-1, finished by all warps)
        int kn = k + STAGES - 1;
        if (kn < KITERS) {
            int koff = kn * BK;
            uint32_t so = (kn & (STAGES - 1)) * STAGE_B;
            cp_async16(aDst + so, aSrc + koff);
            cp_async16(bDst0 + so, bSrc0 + koff);
            cp_async16(bDst1 + so, bSrc1 + koff);
        }
        CP_COMMIT();

        // ---- compute stage k ----
        uint32_t so = (k & (STAGES - 1)) * STAGE_B;
        uint32_t aB = aLds + so;
        uint32_t bB = bLds + so;
        // chain select: stages 0-11 -> chain 0, 12-23 -> chain 1
        uint32_t (*acc)[8][2] = (k < KITERS / 2) ? acch[0] : acch[1];
#pragma unroll
        for (int ks = 0; ks < 2; ks++) {
            uint32_t a[2][4];
            LDSM_X4(a[0][0], a[0][1], a[0][2], a[0][3], aB + ks * 32);
            LDSM_X4(a[1][0], a[1][1], a[1][2], a[1][3], aB + 16 * AROW_B + ks * 32);
            uint32_t b[8][2];
#pragma unroll
            for (int p = 0; p < 4; p++) {
                LDSM_X4(b[2 * p][0], b[2 * p][1], b[2 * p + 1][0], b[2 * p + 1][1],
                        bB + p * (16 * AROW_B) + ks * 32);
            }
#pragma unroll
            for (int mi = 0; mi < 2; mi++)
#pragma unroll
                for (int nj = 0; nj < 8; nj++)
                    MMA16816_F16(acc[mi][nj], a[mi][0], a[mi][1], a[mi][2], a[mi][3],
                                 b[nj][0], b[nj][1]);
        }
    }

    // ---- epilogue: combine chains in fp32, add bias, store ----
#pragma unroll
    for (int nj = 0; nj < 8; nj++) {
        int c = n0 + warp_n * 64 + nj * 8 + 2 * (lane & 3);
        float2 bb = *reinterpret_cast<const float2*>(bias + c);
#pragma unroll
        for (int mi = 0; mi < 2; mi++) {
            int r = m0 + warp_m * 32 + mi * 16 + (lane >> 2);
            float2 c00 = __half22float2(*reinterpret_cast<__half2*>(&acch[0][mi][nj][0]));
            float2 c01 = __half22float2(*reinterpret_cast<__half2*>(&acch[0][mi][nj][1]));
            float2 c10 = __half22float2(*reinterpret_cast<__half2*>(&acch[1][mi][nj][0]));
            float2 c11 = __half22float2(*reinterpret_cast<__half2*>(&acch[1][mi][nj][1]));
            float2 v0, v1;
            v0.x = c00.x + c10.x + bb.x;
            v0.y = c00.y + c10.y + bb.y;
            v1.x = c01.x + c11.x + bb.x;
            v1.y = c01.y + c11.y + bb.y;
            *reinterpret_cast<float2*>(out + (size_t)r * NDIM + c) = v0;
            *reinterpret_cast<float2*>(out + (size_t)(r + 8) * NDIM + c) = v1;
        }
    }
}

// ---------------- launch ----------------
extern "C" void kernel_launch(void* const* d_in, const int* in_sizes, int n_in,
                              void* d_out, int out_size) {
    (void)in_sizes; (void)n_in; (void)out_size;
    const float* x   = (const float*)d_in[0];
    const float* Wq  = (const float*)d_in[1];
    const float* b   = (const float*)d_in[2];
    const float* Aq  = (const float*)d_in[3];
    const float* Bq  = (const float*)d_in[4];
    const float* Av  = (const float*)d_in[5];
    const float* Bv  = (const float*)d_in[6];
    const float* s0  = (const float*)d_in[7];
    float* out = (float*)d_out;

    __half *xh, *wh;
    cudaGetSymbolAddress((void**)&xh, g_Xh);
    cudaGetSymbolAddress((void**)&wh, g_Wh);

    prep_w_kernel<<<(NDIM * KDIM) / 256, 256>>>(Wq, Aq, Bq, Av, Bv, s0);
    prep_x_kernel<<<(int)(((size_t)MDIM * KDIM / 8) / 256), 256>>>(
        (const float4*)x);

    cudaFuncSetAttribute(gemm_f16_kernel,
                         cudaFuncAttributeMaxDynamicSharedMemorySize, SMEM_TOTAL);
    gemm_f16_kernel<<<dim3(NDIM / BN, MDIM / BM, 1), 512, SMEM_TOTAL>>>(
        xh, wh, b, out);
}